// round 1
// baseline (speedup 1.0000x reference)
#include <cuda_runtime.h>
#include <cuda_bf16.h>
#include <math.h>

// Problem constants
#define BB   8
#define DIM  128
#define HH   64
#define WW   64
#define HW   4096          // 64*64
#define KK   7
#define PADK 3
#define GG   8             // groups
#define GC   16            // channels per group
#define C1   32            // DIM/RED
#define C2   392           // K*K*G
#define NPIX 32768         // B*H*W

// -------- scratch (device globals; no runtime allocation) --------
__device__ float g_t[BB * C1 * HW];          // conv1+bn+relu output, NCHW (4 MB)
__device__ float g_wgt[BB * C2 * HW];        // conv2 output (involution weights), NCHW (51 MB)
__device__ float g_y[NPIX * DIM];            // involution output, NHWC (17 MB)
__device__ float g_h[512 * 256 * 64];        // pw1+gelu output, tile-major [tile][f][p] (34 MB)

// =====================================================================
// K1: t = relu(bn(conv1(x)))   — BN folded into weights/bias
// grid 64, block 256, 2 pixels/thread
// =====================================================================
__global__ void k1_conv1(const float* __restrict__ x,
                         const float* __restrict__ w1,
                         const float* __restrict__ b1,
                         const float* __restrict__ bng,
                         const float* __restrict__ bnb,
                         const float* __restrict__ bnm,
                         const float* __restrict__ bnv) {
    __shared__ float ws[C1 * DIM];
    __shared__ float ss[C1];
    __shared__ float bs[C1];
    int tid = threadIdx.x;
    if (tid < C1) {
        float sc = bng[tid] * rsqrtf(bnv[tid] + 1e-5f);
        ss[tid] = sc;
        bs[tid] = b1[tid] * sc + bnb[tid] - bnm[tid] * sc;
    }
    __syncthreads();
    for (int i = tid; i < C1 * DIM; i += 256) ws[i] = w1[i] * ss[i >> 7];
    __syncthreads();

    int pix0 = blockIdx.x * 512 + tid;      // 512 consecutive pixels per block
    int b    = pix0 >> 12;                  // same b for whole block (512 | 4096)
    int pin0 = pix0 & 4095;
    int pin1 = pin0 + 256;
    const float* xb = x + b * DIM * HW;

    float acc0[C1], acc1[C1];
#pragma unroll
    for (int o = 0; o < C1; o++) { acc0[o] = 0.f; acc1[o] = 0.f; }

    for (int c = 0; c < DIM; c += 4) {
        float x00 = __ldg(xb + (c + 0) * HW + pin0);
        float x01 = __ldg(xb + (c + 1) * HW + pin0);
        float x02 = __ldg(xb + (c + 2) * HW + pin0);
        float x03 = __ldg(xb + (c + 3) * HW + pin0);
        float x10 = __ldg(xb + (c + 0) * HW + pin1);
        float x11 = __ldg(xb + (c + 1) * HW + pin1);
        float x12 = __ldg(xb + (c + 2) * HW + pin1);
        float x13 = __ldg(xb + (c + 3) * HW + pin1);
#pragma unroll
        for (int o = 0; o < C1; o++) {
            float4 w = *(const float4*)(ws + o * DIM + c);
            acc0[o] += w.x * x00; acc0[o] += w.y * x01;
            acc0[o] += w.z * x02; acc0[o] += w.w * x03;
            acc1[o] += w.x * x10; acc1[o] += w.y * x11;
            acc1[o] += w.z * x12; acc1[o] += w.w * x13;
        }
    }
    float* tb = g_t + b * C1 * HW;
#pragma unroll
    for (int o = 0; o < C1; o++) {
        tb[o * HW + pin0] = fmaxf(acc0[o] + bs[o], 0.f);
        tb[o * HW + pin1] = fmaxf(acc1[o] + bs[o], 0.f);
    }
}

// =====================================================================
// K2: wgt = conv2(t)   (392 outputs per pixel)
// grid 512 (64-pixel tiles), block 256, 4x4 register blocking
// dyn smem: ws[392*32] + bsm[392] + ts[32*64]
// =====================================================================
__global__ void k2_conv2(const float* __restrict__ w2,
                         const float* __restrict__ b2) {
    extern __shared__ float sm2[];
    float* ws  = sm2;                 // 12544
    float* bsm = sm2 + 12544;         // 392
    float* ts  = sm2 + 12936;         // 2048
    int tid = threadIdx.x;

    for (int i = tid; i < C2 * C1; i += 256) ws[i] = w2[i];
    for (int i = tid; i < C2; i += 256)      bsm[i] = b2[i];

    int pixbase = blockIdx.x * 64;
    int b   = pixbase >> 12;
    int pin = pixbase & 4095;
    const float* tb = g_t + b * C1 * HW + pin;
    for (int i = tid; i < C1 * 64; i += 256) {
        int c = i >> 6, p = i & 63;
        ts[i] = tb[c * HW + p];
    }
    __syncthreads();

    int pg = tid & 15;   int p0 = pg * 4;
    int fo = tid >> 4;   // 0..15
    float* wout = g_wgt + b * C2 * HW + pin + p0;

    for (int ob = fo * 4; ob < C2; ob += 64) {
        float a[4][4];
#pragma unroll
        for (int k = 0; k < 4; k++)
#pragma unroll
            for (int l = 0; l < 4; l++) a[k][l] = 0.f;

#pragma unroll 4
        for (int c = 0; c < C1; c++) {
            float4 tv = *(const float4*)(ts + c * 64 + p0);
#pragma unroll
            for (int k = 0; k < 4; k++) {
                float wv = ws[(ob + k) * C1 + c];
                a[k][0] += wv * tv.x; a[k][1] += wv * tv.y;
                a[k][2] += wv * tv.z; a[k][3] += wv * tv.w;
            }
        }
#pragma unroll
        for (int k = 0; k < 4; k++) {
            float bb = bsm[ob + k];
            float4 r = make_float4(a[k][0] + bb, a[k][1] + bb,
                                   a[k][2] + bb, a[k][3] + bb);
            *(float4*)(wout + (ob + k) * HW) = r;
        }
    }
}

// =====================================================================
// K3: involution.  grid (8 strips, 8 groups, 8 batch), block 256.
// smem x halo tile: 16ch x 14rows x 72cols (zero-padded)
// writes y in NHWC to g_y
// =====================================================================
#define XS_ROW 72
#define XS_CH  (14 * 72)
__global__ void k3_involution(const float* __restrict__ x) {
    extern __shared__ float xs[];     // 16*14*72 = 16128 floats
    int tid = threadIdx.x;
    int h0 = blockIdx.x * 8;
    int g  = blockIdx.y;
    int b  = blockIdx.z;

    for (int i = tid; i < GC * XS_CH; i += 256) xs[i] = 0.f;
    __syncthreads();

    // load valid interior
    const float* xg = x + (b * DIM + g * GC) * HW;
    for (int idx = tid; idx < GC * 14 * 64; idx += 256) {
        int gc = idx / (14 * 64);
        int rem = idx - gc * (14 * 64);
        int rr = rem >> 6;
        int ww = rem & 63;
        int hh = h0 - 3 + rr;
        if (hh >= 0 && hh < HH)
            xs[gc * XS_CH + rr * XS_ROW + ww + 3] = xg[gc * HW + hh * WW + ww];
    }
    __syncthreads();

    for (int pi = 0; pi < 2; pi++) {
        int pl = tid + pi * 256;          // 0..511
        int r = pl >> 6, w = pl & 63;
        float acc[GC];
#pragma unroll
        for (int gc = 0; gc < GC; gc++) acc[gc] = 0.f;

        const float* wp = g_wgt + (b * C2 + g * 49) * HW + (h0 + r) * WW + w;
        for (int i = 0; i < KK; i++) {
#pragma unroll
            for (int j = 0; j < KK; j++) {
                float wv = __ldg(wp + (i * KK + j) * HW);
                const float* xp = xs + (r + i) * XS_ROW + (w + j);
#pragma unroll
                for (int gc = 0; gc < GC; gc++)
                    acc[gc] += wv * xp[gc * XS_CH];
            }
        }
        float* yo = g_y + (b * HW + (h0 + r) * WW + w) * DIM + g * GC;
#pragma unroll
        for (int q = 0; q < 4; q++) {
            float4 v = make_float4(acc[q*4+0], acc[q*4+1], acc[q*4+2], acc[q*4+3]);
            *(float4*)(yo + q * 4) = v;
        }
    }
}

// =====================================================================
// K4a: LayerNorm + pw1 + exact GELU
// grid 512 (64-pixel tiles), block 256, 8x8 register blocking
// dyn smem: w1s[256*128] + ys[128*64] + lng[128] + lnb[128] + b1s[256]
// h written tile-major: g_h[T*16384 + f*64 + p]
// =====================================================================
__global__ void k4a_ln_pw1(const float* __restrict__ lng_g,
                           const float* __restrict__ lnb_g,
                           const float* __restrict__ p1w,
                           const float* __restrict__ p1b) {
    extern __shared__ float sm4[];
    float* w1s = sm4;                  // 32768
    float* ys  = sm4 + 32768;          // 8192
    float* lng = sm4 + 40960;          // 128
    float* lnb = lng + 128;            // 128
    float* b1s = lnb + 128;            // 256
    int tid = threadIdx.x;
    int T = blockIdx.x;
    int pixbase = T * 64;

    for (int i = tid; i < 256 * 128; i += 256) w1s[i] = p1w[i];
    if (tid < 128) { lng[tid] = lng_g[tid]; lnb[tid] = lnb_g[tid]; }
    if (tid < 256) b1s[tid] = p1b[tid];

    // ---- LayerNorm: 4 threads per pixel ----
    int p    = tid >> 2;
    int lane = tid & 3;
    const float* yp = g_y + (pixbase + p) * DIM + lane * 32;
    float4 yv[8];
    float s = 0.f, q = 0.f;
#pragma unroll
    for (int i = 0; i < 8; i++) {
        yv[i] = *(const float4*)(yp + i * 4);
        s += yv[i].x + yv[i].y + yv[i].z + yv[i].w;
        q += yv[i].x*yv[i].x + yv[i].y*yv[i].y + yv[i].z*yv[i].z + yv[i].w*yv[i].w;
    }
    s += __shfl_xor_sync(0xffffffffu, s, 1, 4);
    s += __shfl_xor_sync(0xffffffffu, s, 2, 4);
    q += __shfl_xor_sync(0xffffffffu, q, 1, 4);
    q += __shfl_xor_sync(0xffffffffu, q, 2, 4);
    float mu   = s * (1.0f / 128.0f);
    float var  = q * (1.0f / 128.0f) - mu * mu;
    float rstd = rsqrtf(var + 1e-6f);
    __syncthreads();   // lng/lnb ready (also w1s)
#pragma unroll
    for (int i = 0; i < 8; i++) {
        int c = lane * 32 + i * 4;
        ys[(c + 0) * 64 + p] = (yv[i].x - mu) * rstd * lng[c + 0] + lnb[c + 0];
        ys[(c + 1) * 64 + p] = (yv[i].y - mu) * rstd * lng[c + 1] + lnb[c + 1];
        ys[(c + 2) * 64 + p] = (yv[i].z - mu) * rstd * lng[c + 2] + lnb[c + 2];
        ys[(c + 3) * 64 + p] = (yv[i].w - mu) * rstd * lng[c + 3] + lnb[c + 3];
    }
    __syncthreads();

    // ---- GEMM: 64 px x 256 f, thread = 8f x 8p ----
    int pg = tid & 7;  int p0 = pg * 8;
    int fg = tid >> 3; int f0 = fg * 8;
    float acc[8][8];
#pragma unroll
    for (int k = 0; k < 8; k++)
#pragma unroll
        for (int l = 0; l < 8; l++) acc[k][l] = 0.f;

#pragma unroll 4
    for (int c = 0; c < 128; c++) {
        float4 ya = *(const float4*)(ys + c * 64 + p0);
        float4 yb = *(const float4*)(ys + c * 64 + p0 + 4);
#pragma unroll
        for (int k = 0; k < 8; k++) {
            float wv = w1s[(f0 + k) * 128 + c];
            acc[k][0] += wv * ya.x; acc[k][1] += wv * ya.y;
            acc[k][2] += wv * ya.z; acc[k][3] += wv * ya.w;
            acc[k][4] += wv * yb.x; acc[k][5] += wv * yb.y;
            acc[k][6] += wv * yb.z; acc[k][7] += wv * yb.w;
        }
    }

    float* hb = g_h + T * 16384;
#pragma unroll
    for (int k = 0; k < 8; k++) {
        int f = f0 + k;
        float bb = b1s[f];
        float v[8];
#pragma unroll
        for (int l = 0; l < 8; l++) {
            float z = acc[k][l] + bb;
            v[l] = 0.5f * z * (1.0f + erff(z * 0.70710678118654752f));
        }
        *(float4*)(hb + f * 64 + p0)     = make_float4(v[0], v[1], v[2], v[3]);
        *(float4*)(hb + f * 64 + p0 + 4) = make_float4(v[4], v[5], v[6], v[7]);
    }
}

// =====================================================================
// K4b: pw2 + bias + residual, output NCHW
// grid 256 (128-pixel tiles), block 256, 8x8 blocking
// dyn smem: hs[256*128] + w2s[128*128] + b2s[128]
// =====================================================================
__global__ void k4b_pw2(const float* __restrict__ p2w,
                        const float* __restrict__ p2b,
                        const float* __restrict__ x,
                        float* __restrict__ out) {
    extern __shared__ float sm5[];
    float* hs  = sm5;                  // 32768
    float* w2s = sm5 + 32768;          // 16384 (one 128-f chunk, layout [c][fl])
    float* b2s = sm5 + 49152;          // 128
    int tid = threadIdx.x;
    int T = blockIdx.x;
    int pixbase = T * 128;
    int b   = pixbase >> 12;
    int pin = pixbase & 4095;

    // load h tile: [256 f][128 p] from two 64-pixel sub-tiles
    for (int i = tid; i < 256 * 128; i += 256) {
        int f = i >> 7, p = i & 127;
        hs[i] = g_h[(2 * T + (p >> 6)) * 16384 + f * 64 + (p & 63)];
    }
    if (tid < 128) b2s[tid] = p2b[tid];

    int pg = tid & 15;  int p0 = pg * 8;
    int fg = tid >> 4;  int c0 = fg * 8;
    float acc[8][8];
#pragma unroll
    for (int k = 0; k < 8; k++)
#pragma unroll
        for (int l = 0; l < 8; l++) acc[k][l] = 0.f;

    for (int half = 0; half < 2; half++) {
        __syncthreads();   // hs ready (iter0) / previous compute done (iter1)
        int foff = half * 128;
        for (int i = tid; i < 128 * 128; i += 256) {
            int c = i >> 7, fl = i & 127;
            w2s[i] = p2w[c * 256 + foff + fl];
        }
        __syncthreads();

#pragma unroll 4
        for (int fl = 0; fl < 128; fl++) {
            int f = foff + fl;
            float4 ha = *(const float4*)(hs + f * 128 + p0);
            float4 hb4 = *(const float4*)(hs + f * 128 + p0 + 4);
#pragma unroll
            for (int k = 0; k < 8; k++) {
                float wv = w2s[(c0 + k) * 128 + fl];
                acc[k][0] += wv * ha.x;  acc[k][1] += wv * ha.y;
                acc[k][2] += wv * ha.z;  acc[k][3] += wv * ha.w;
                acc[k][4] += wv * hb4.x; acc[k][5] += wv * hb4.y;
                acc[k][6] += wv * hb4.z; acc[k][7] += wv * hb4.w;
            }
        }
    }

    // epilogue: + bias + identity, write NCHW
#pragma unroll
    for (int k = 0; k < 8; k++) {
        int c = c0 + k;
        int base = (b * DIM + c) * HW + pin + p0;
        float bb = b2s[c];
        float4 i0 = *(const float4*)(x + base);
        float4 i1 = *(const float4*)(x + base + 4);
        float4 r0 = make_float4(acc[k][0] + bb + i0.x, acc[k][1] + bb + i0.y,
                                acc[k][2] + bb + i0.z, acc[k][3] + bb + i0.w);
        float4 r1 = make_float4(acc[k][4] + bb + i1.x, acc[k][5] + bb + i1.y,
                                acc[k][6] + bb + i1.z, acc[k][7] + bb + i1.w);
        *(float4*)(out + base)     = r0;
        *(float4*)(out + base + 4) = r1;
    }
}

// =====================================================================
extern "C" void kernel_launch(void* const* d_in, const int* in_sizes, int n_in,
                              void* d_out, int out_size) {
    const float* x    = (const float*)d_in[0];
    const float* c1w  = (const float*)d_in[1];
    const float* c1b  = (const float*)d_in[2];
    const float* bng  = (const float*)d_in[3];
    const float* bnb  = (const float*)d_in[4];
    const float* bnm  = (const float*)d_in[5];
    const float* bnv  = (const float*)d_in[6];
    const float* c2w  = (const float*)d_in[7];
    const float* c2b  = (const float*)d_in[8];
    const float* lng  = (const float*)d_in[9];
    const float* lnb  = (const float*)d_in[10];
    const float* p1w  = (const float*)d_in[11];
    const float* p1b  = (const float*)d_in[12];
    const float* p2w  = (const float*)d_in[13];
    const float* p2b  = (const float*)d_in[14];
    float* out = (float*)d_out;

    const int SM_K2  = (12544 + 392 + 2048) * 4;          // 59936
    const int SM_K3  = 16 * 14 * 72 * 4;                  // 64512
    const int SM_K4A = (32768 + 8192 + 512) * 4;          // 165888
    const int SM_K4B = (32768 + 16384 + 128) * 4;         // 197120

    cudaFuncSetAttribute(k2_conv2,     cudaFuncAttributeMaxDynamicSharedMemorySize, SM_K2);
    cudaFuncSetAttribute(k3_involution,cudaFuncAttributeMaxDynamicSharedMemorySize, SM_K3);
    cudaFuncSetAttribute(k4a_ln_pw1,   cudaFuncAttributeMaxDynamicSharedMemorySize, SM_K4A);
    cudaFuncSetAttribute(k4b_pw2,      cudaFuncAttributeMaxDynamicSharedMemorySize, SM_K4B);

    k1_conv1<<<64, 256>>>(x, c1w, c1b, bng, bnb, bnm, bnv);
    k2_conv2<<<512, 256, SM_K2>>>(c2w, c2b);
    k3_involution<<<dim3(8, 8, 8), 256, SM_K3>>>(x);
    k4a_ln_pw1<<<512, 256, SM_K4A>>>(lng, lnb, p1w, p1b);
    k4b_pw2<<<256, 256, SM_K4B>>>(p2w, p2b, x, out);
}

// round 2
// speedup vs baseline: 1.3282x; 1.3282x over previous
#include <cuda_runtime.h>
#include <math.h>

// Problem constants
#define BB   8
#define DIM  128
#define HH   64
#define WW   64
#define HW   4096
#define KK   7
#define GG   8
#define GC   16
#define C1   32
#define C2   392
#define NPIX 32768

// -------- scratch (device globals) --------
__device__ float g_t[BB * C1 * HW];          // conv1+bn+relu, NCHW (4 MB)
__device__ float g_wgt[BB * C2 * HW];        // involution weights, NCHW (51 MB)
__device__ float g_y[NPIX * DIM];            // involution out, NHWC (17 MB)
__device__ float g_h[256 * NPIX];            // pw1+gelu out, [f][px] (33.5 MB)

// -------- tf32 mma helpers --------
__device__ __forceinline__ unsigned f2tf(float f) {
    unsigned r; asm("cvt.rna.tf32.f32 %0, %1;" : "=r"(r) : "f"(f)); return r;
}
__device__ __forceinline__ void mma8(float* c, unsigned a0, unsigned a1,
                                     unsigned a2, unsigned a3,
                                     unsigned b0, unsigned b1) {
    asm volatile(
        "mma.sync.aligned.m16n8k8.row.col.f32.tf32.tf32.f32 "
        "{%0,%1,%2,%3}, {%4,%5,%6,%7}, {%8,%9}, {%0,%1,%2,%3};\n"
        : "+f"(c[0]), "+f"(c[1]), "+f"(c[2]), "+f"(c[3])
        : "r"(a0), "r"(a1), "r"(a2), "r"(a3), "r"(b0), "r"(b1));
}

// =====================================================================
// K1: t = relu(bn(conv1(x)))  — MMA, M=32 outs, N=128 px/block, K=128
// grid 256, block 256. smem: wA[32][132] + xs[128][136] + bias
// =====================================================================
__global__ __launch_bounds__(256) void k1_conv1(
    const float* __restrict__ x,  const float* __restrict__ w1,
    const float* __restrict__ b1, const float* __restrict__ bng,
    const float* __restrict__ bnb, const float* __restrict__ bnm,
    const float* __restrict__ bnv) {
    extern __shared__ unsigned smu[];
    unsigned* wA = smu;                 // 32*132
    unsigned* xs = smu + 32 * 132;      // 128*136
    float* bs = (float*)(xs + 128 * 136);   // 32
    float* ss = bs + 32;                    // 32
    int tid = threadIdx.x;

    if (tid < 32) {
        float sc = bng[tid] * rsqrtf(bnv[tid] + 1e-5f);
        ss[tid] = sc;
        bs[tid] = b1[tid] * sc + bnb[tid] - bnm[tid] * sc;
    }
    __syncthreads();
    for (int i = tid; i < 32 * 128; i += 256) {
        int o = i >> 7, c = i & 127;
        wA[o * 132 + c] = f2tf(w1[i] * ss[o]);
    }
    int pb = blockIdx.x * 128, b = pb >> 12, pin = pb & 4095;
    const float* xb = x + b * DIM * HW + pin;
    for (int i = tid; i < 128 * 128; i += 256) {
        int c = i >> 7, p = i & 127;
        xs[c * 136 + p] = f2tf(xb[c * HW + p]);
    }
    __syncthreads();

    int wid = tid >> 5, lane = tid & 31, gid = lane >> 2, ctid = lane & 3;
    int m = wid & 1, ng = wid >> 1;   // warp: 16 outs x 32 px
    int px0 = ng * 32;
    float acc[4][4];
#pragma unroll
    for (int a = 0; a < 4; a++)
#pragma unroll
        for (int b2 = 0; b2 < 4; b2++) acc[a][b2] = 0.f;

#pragma unroll
    for (int s = 0; s < 16; s++) {
        int k0 = s * 8;
        const unsigned* ap = wA + (m * 16 + gid) * 132 + k0 + ctid;
        unsigned a0 = ap[0], a1 = ap[8 * 132], a2 = ap[4], a3 = ap[8 * 132 + 4];
#pragma unroll
        for (int nt = 0; nt < 4; nt++) {
            int pxn = px0 + nt * 8 + gid;
            unsigned b0 = xs[(k0 + ctid) * 136 + pxn];
            unsigned b1v = xs[(k0 + ctid + 4) * 136 + pxn];
            mma8(acc[nt], a0, a1, a2, a3, b0, b1v);
        }
    }
    float* tb = g_t + b * C1 * HW + pin;
    int o0 = m * 16 + gid;
#pragma unroll
    for (int nt = 0; nt < 4; nt++) {
        int px = px0 + nt * 8 + 2 * ctid;
        float b0v = bs[o0], b1v = bs[o0 + 8];
        *(float2*)(tb + o0 * HW + px) =
            make_float2(fmaxf(acc[nt][0] + b0v, 0.f), fmaxf(acc[nt][1] + b0v, 0.f));
        *(float2*)(tb + (o0 + 8) * HW + px) =
            make_float2(fmaxf(acc[nt][2] + b1v, 0.f), fmaxf(acc[nt][3] + b1v, 0.f));
    }
}

// =====================================================================
// K2: wgt = conv2(t) — MMA, M=128 outs/block (392 padded to 512),
// N=128 px/block, K=32. grid (256,4), block 256.
// =====================================================================
__global__ __launch_bounds__(256) void k2_conv2(
    const float* __restrict__ w2, const float* __restrict__ b2) {
    extern __shared__ unsigned smu[];
    unsigned* wA = smu;                 // 128*36
    unsigned* ts = smu + 128 * 36;      // 32*136
    float* bsm = (float*)(ts + 32 * 136);   // 128
    int tid = threadIdx.x;
    int o0 = blockIdx.y * 128;

    for (int i = tid; i < 128 * 32; i += 256) {
        int o = i >> 5, c = i & 31;
        int go = o0 + o;
        wA[o * 36 + c] = f2tf(go < C2 ? w2[go * C1 + c] : 0.f);
    }
    if (tid < 128) bsm[tid] = (o0 + tid < C2) ? b2[o0 + tid] : 0.f;
    int pb = blockIdx.x * 128, b = pb >> 12, pin = pb & 4095;
    const float* tbp = g_t + b * C1 * HW + pin;
    for (int i = tid; i < 32 * 128; i += 256) {
        int c = i >> 7, p = i & 127;
        ts[c * 136 + p] = f2tf(tbp[c * HW + p]);
    }
    __syncthreads();

    int wid = tid >> 5, lane = tid & 31, gid = lane >> 2, ctid = lane & 3;
    int m = wid & 3, ng = wid >> 2;   // warp: 32 outs x 64 px
    float acc[2][8][4];
#pragma unroll
    for (int mt = 0; mt < 2; mt++)
#pragma unroll
        for (int nt = 0; nt < 8; nt++)
#pragma unroll
            for (int q = 0; q < 4; q++) acc[mt][nt][q] = 0.f;

#pragma unroll
    for (int s = 0; s < 4; s++) {
        int k0 = s * 8;
        unsigned a[2][4];
#pragma unroll
        for (int mt = 0; mt < 2; mt++) {
            const unsigned* ap = wA + (m * 32 + mt * 16 + gid) * 36 + k0 + ctid;
            a[mt][0] = ap[0]; a[mt][1] = ap[8 * 36];
            a[mt][2] = ap[4]; a[mt][3] = ap[8 * 36 + 4];
        }
#pragma unroll
        for (int nt = 0; nt < 8; nt++) {
            int pxn = ng * 64 + nt * 8 + gid;
            unsigned b0 = ts[(k0 + ctid) * 136 + pxn];
            unsigned b1v = ts[(k0 + ctid + 4) * 136 + pxn];
#pragma unroll
            for (int mt = 0; mt < 2; mt++)
                mma8(acc[mt][nt], a[mt][0], a[mt][1], a[mt][2], a[mt][3], b0, b1v);
        }
    }
    float* wout = g_wgt + b * C2 * HW + pin;
#pragma unroll
    for (int mt = 0; mt < 2; mt++) {
        int orow = m * 32 + mt * 16 + gid;
        int go0 = o0 + orow, go1 = go0 + 8;
        float bb0 = bsm[orow], bb1 = bsm[orow + 8];
#pragma unroll
        for (int nt = 0; nt < 8; nt++) {
            int px = ng * 64 + nt * 8 + 2 * ctid;
            if (go0 < C2)
                *(float2*)(wout + go0 * HW + px) =
                    make_float2(acc[mt][nt][0] + bb0, acc[mt][nt][1] + bb0);
            if (go1 < C2)
                *(float2*)(wout + go1 * HW + px) =
                    make_float2(acc[mt][nt][2] + bb1, acc[mt][nt][3] + bb1);
        }
    }
}

// =====================================================================
// K3: involution (fp32 stencil).  grid (8,8,8), block 256.
// =====================================================================
#define XS_ROW 72
#define XS_CH  (14 * 72)
__global__ void k3_involution(const float* __restrict__ x) {
    extern __shared__ float xs[];
    int tid = threadIdx.x;
    int h0 = blockIdx.x * 8;
    int g  = blockIdx.y;
    int b  = blockIdx.z;

    for (int i = tid; i < GC * XS_CH; i += 256) xs[i] = 0.f;
    __syncthreads();
    const float* xg = x + (b * DIM + g * GC) * HW;
    for (int idx = tid; idx < GC * 14 * 64; idx += 256) {
        int gc = idx / (14 * 64);
        int rem = idx - gc * (14 * 64);
        int rr = rem >> 6, ww = rem & 63;
        int hh = h0 - 3 + rr;
        if (hh >= 0 && hh < HH)
            xs[gc * XS_CH + rr * XS_ROW + ww + 3] = xg[gc * HW + hh * WW + ww];
    }
    __syncthreads();

    for (int pi = 0; pi < 2; pi++) {
        int pl = tid + pi * 256;
        int r = pl >> 6, w = pl & 63;
        float acc[GC];
#pragma unroll
        for (int gc = 0; gc < GC; gc++) acc[gc] = 0.f;
        const float* wp = g_wgt + (b * C2 + g * 49) * HW + (h0 + r) * WW + w;
        for (int i = 0; i < KK; i++) {
#pragma unroll
            for (int j = 0; j < KK; j++) {
                float wv = __ldg(wp + (i * KK + j) * HW);
                const float* xp = xs + (r + i) * XS_ROW + (w + j);
#pragma unroll
                for (int gc = 0; gc < GC; gc++)
                    acc[gc] += wv * xp[gc * XS_CH];
            }
        }
        float* yo = g_y + (b * HW + (h0 + r) * WW + w) * DIM + g * GC;
#pragma unroll
        for (int q = 0; q < 4; q++)
            *(float4*)(yo + q * 4) = make_float4(acc[q*4], acc[q*4+1], acc[q*4+2], acc[q*4+3]);
    }
}

// =====================================================================
// K4a: LN + pw1 + exact GELU — MMA. M=128 f/block (of 256), N=128 px,
// K=128. grid (256,2), block 256.
// =====================================================================
__global__ __launch_bounds__(256) void k4a_ln_pw1(
    const float* __restrict__ lng_g, const float* __restrict__ lnb_g,
    const float* __restrict__ p1w,   const float* __restrict__ p1b) {
    extern __shared__ unsigned smu[];
    unsigned* w1s = smu;                 // 128*132
    unsigned* ys  = smu + 128 * 132;     // 128*136
    float* lng = (float*)(ys + 128 * 136);  // 128
    float* lnb = lng + 128;
    float* b1s = lnb + 128;
    int tid = threadIdx.x;
    int f0 = blockIdx.y * 128;
    int pb = blockIdx.x * 128;

    for (int i = tid; i < 128 * 128; i += 256) {
        int f = i >> 7, c = i & 127;
        w1s[f * 132 + c] = f2tf(p1w[(f0 + f) * 128 + c]);
    }
    if (tid < 128) {
        lng[tid] = lng_g[tid]; lnb[tid] = lnb_g[tid]; b1s[tid] = p1b[f0 + tid];
    }
    __syncthreads();

    // LayerNorm: 2 threads / pixel
    {
        int p = tid >> 1, half = tid & 1;
        const float* yp = g_y + (pb + p) * DIM + half * 64;
        float4 v[16];
        float s = 0.f, q = 0.f;
#pragma unroll
        for (int i = 0; i < 16; i++) {
            v[i] = *(const float4*)(yp + i * 4);
            s += v[i].x + v[i].y + v[i].z + v[i].w;
            q += v[i].x*v[i].x + v[i].y*v[i].y + v[i].z*v[i].z + v[i].w*v[i].w;
        }
        s += __shfl_xor_sync(0xffffffffu, s, 1);
        q += __shfl_xor_sync(0xffffffffu, q, 1);
        float mu = s * (1.f / 128.f);
        float var = q * (1.f / 128.f) - mu * mu;
        float rs = rsqrtf(var + 1e-6f);
#pragma unroll
        for (int i = 0; i < 16; i++) {
            int c = half * 64 + i * 4;
            ys[(c+0)*136 + p] = f2tf((v[i].x - mu) * rs * lng[c+0] + lnb[c+0]);
            ys[(c+1)*136 + p] = f2tf((v[i].y - mu) * rs * lng[c+1] + lnb[c+1]);
            ys[(c+2)*136 + p] = f2tf((v[i].z - mu) * rs * lng[c+2] + lnb[c+2]);
            ys[(c+3)*136 + p] = f2tf((v[i].w - mu) * rs * lng[c+3] + lnb[c+3]);
        }
    }
    __syncthreads();

    int wid = tid >> 5, lane = tid & 31, gid = lane >> 2, ctid = lane & 3;
    int m = wid & 3, ng = wid >> 2;
    float acc[2][8][4];
#pragma unroll
    for (int mt = 0; mt < 2; mt++)
#pragma unroll
        for (int nt = 0; nt < 8; nt++)
#pragma unroll
            for (int q = 0; q < 4; q++) acc[mt][nt][q] = 0.f;

#pragma unroll
    for (int s8 = 0; s8 < 16; s8++) {
        int k0 = s8 * 8;
        unsigned a[2][4];
#pragma unroll
        for (int mt = 0; mt < 2; mt++) {
            const unsigned* ap = w1s + (m * 32 + mt * 16 + gid) * 132 + k0 + ctid;
            a[mt][0] = ap[0]; a[mt][1] = ap[8 * 132];
            a[mt][2] = ap[4]; a[mt][3] = ap[8 * 132 + 4];
        }
#pragma unroll
        for (int nt = 0; nt < 8; nt++) {
            int pxn = ng * 64 + nt * 8 + gid;
            unsigned b0 = ys[(k0 + ctid) * 136 + pxn];
            unsigned b1v = ys[(k0 + ctid + 4) * 136 + pxn];
#pragma unroll
            for (int mt = 0; mt < 2; mt++)
                mma8(acc[mt][nt], a[mt][0], a[mt][1], a[mt][2], a[mt][3], b0, b1v);
        }
    }
    const float ISQ2 = 0.70710678118654752f;
#pragma unroll
    for (int mt = 0; mt < 2; mt++) {
        int frow = m * 32 + mt * 16 + gid;
        float bb0 = b1s[frow], bb1 = b1s[frow + 8];
        int fg0 = f0 + frow, fg1 = fg0 + 8;
#pragma unroll
        for (int nt = 0; nt < 8; nt++) {
            int px = pb + ng * 64 + nt * 8 + 2 * ctid;
            float z0 = acc[mt][nt][0] + bb0, z1 = acc[mt][nt][1] + bb0;
            float z2 = acc[mt][nt][2] + bb1, z3 = acc[mt][nt][3] + bb1;
            float g0 = 0.5f * z0 * (1.f + erff(z0 * ISQ2));
            float g1 = 0.5f * z1 * (1.f + erff(z1 * ISQ2));
            float g2 = 0.5f * z2 * (1.f + erff(z2 * ISQ2));
            float g3 = 0.5f * z3 * (1.f + erff(z3 * ISQ2));
            *(float2*)(g_h + fg0 * NPIX + px) = make_float2(g0, g1);
            *(float2*)(g_h + fg1 * NPIX + px) = make_float2(g2, g3);
        }
    }
}

// =====================================================================
// K4b: pw2 + bias + residual — MMA. M=128 c, N=128 px/block, K=256 in
// 2 chunks. grid 256, block 256.
// =====================================================================
__global__ __launch_bounds__(256) void k4b_pw2(
    const float* __restrict__ p2w, const float* __restrict__ p2b,
    const float* __restrict__ x,   float* __restrict__ out) {
    extern __shared__ unsigned smu[];
    unsigned* w2s = smu;                 // 128*132
    unsigned* hs  = smu + 128 * 132;     // 128*136
    float* b2s = (float*)(hs + 128 * 136);
    int tid = threadIdx.x;
    int pb = blockIdx.x * 128, b = pb >> 12, pin = pb & 4095;
    if (tid < 128) b2s[tid] = p2b[tid];

    int wid = tid >> 5, lane = tid & 31, gid = lane >> 2, ctid = lane & 3;
    int m = wid & 3, ng = wid >> 2;
    float acc[2][8][4];
#pragma unroll
    for (int mt = 0; mt < 2; mt++)
#pragma unroll
        for (int nt = 0; nt < 8; nt++)
#pragma unroll
            for (int q = 0; q < 4; q++) acc[mt][nt][q] = 0.f;

    for (int kc = 0; kc < 2; kc++) {
        __syncthreads();
        for (int i = tid; i < 128 * 128; i += 256) {
            int c = i >> 7, fl = i & 127;
            w2s[c * 132 + fl] = f2tf(p2w[c * 256 + kc * 128 + fl]);
        }
        for (int i = tid; i < 128 * 128; i += 256) {
            int f = i >> 7, p = i & 127;
            hs[f * 136 + p] = f2tf(g_h[(kc * 128 + f) * NPIX + pb + p]);
        }
        __syncthreads();
#pragma unroll
        for (int s8 = 0; s8 < 16; s8++) {
            int k0 = s8 * 8;
            unsigned a[2][4];
#pragma unroll
            for (int mt = 0; mt < 2; mt++) {
                const unsigned* ap = w2s + (m * 32 + mt * 16 + gid) * 132 + k0 + ctid;
                a[mt][0] = ap[0]; a[mt][1] = ap[8 * 132];
                a[mt][2] = ap[4]; a[mt][3] = ap[8 * 132 + 4];
            }
#pragma unroll
            for (int nt = 0; nt < 8; nt++) {
                int pxn = ng * 64 + nt * 8 + gid;
                unsigned b0 = hs[(k0 + ctid) * 136 + pxn];
                unsigned b1v = hs[(k0 + ctid + 4) * 136 + pxn];
#pragma unroll
                for (int mt = 0; mt < 2; mt++)
                    mma8(acc[mt][nt], a[mt][0], a[mt][1], a[mt][2], a[mt][3], b0, b1v);
            }
        }
    }
#pragma unroll
    for (int mt = 0; mt < 2; mt++) {
        int crow = m * 32 + mt * 16 + gid;
        float bb0 = b2s[crow], bb1 = b2s[crow + 8];
#pragma unroll
        for (int nt = 0; nt < 8; nt++) {
            int px = ng * 64 + nt * 8 + 2 * ctid;
            int base0 = (b * DIM + crow) * HW + pin + px;
            int base1 = base0 + 8 * HW;
            float2 x0 = *(const float2*)(x + base0);
            float2 x1 = *(const float2*)(x + base1);
            *(float2*)(out + base0) =
                make_float2(acc[mt][nt][0] + bb0 + x0.x, acc[mt][nt][1] + bb0 + x0.y);
            *(float2*)(out + base1) =
                make_float2(acc[mt][nt][2] + bb1 + x1.x, acc[mt][nt][3] + bb1 + x1.y);
        }
    }
}

// =====================================================================
extern "C" void kernel_launch(void* const* d_in, const int* in_sizes, int n_in,
                              void* d_out, int out_size) {
    const float* x    = (const float*)d_in[0];
    const float* c1w  = (const float*)d_in[1];
    const float* c1b  = (const float*)d_in[2];
    const float* bng  = (const float*)d_in[3];
    const float* bnb  = (const float*)d_in[4];
    const float* bnm  = (const float*)d_in[5];
    const float* bnv  = (const float*)d_in[6];
    const float* c2w  = (const float*)d_in[7];
    const float* c2b  = (const float*)d_in[8];
    const float* lng  = (const float*)d_in[9];
    const float* lnb  = (const float*)d_in[10];
    const float* p1w  = (const float*)d_in[11];
    const float* p1b  = (const float*)d_in[12];
    const float* p2w  = (const float*)d_in[13];
    const float* p2b  = (const float*)d_in[14];
    float* out = (float*)d_out;

    const int SM_K1  = (32 * 132 + 128 * 136 + 64) * 4;
    const int SM_K2  = (128 * 36 + 32 * 136 + 128) * 4;
    const int SM_K3  = 16 * 14 * 72 * 4;
    const int SM_K4A = (128 * 132 + 128 * 136 + 384) * 4;
    const int SM_K4B = (128 * 132 + 128 * 136 + 128) * 4;

    cudaFuncSetAttribute(k1_conv1,      cudaFuncAttributeMaxDynamicSharedMemorySize, SM_K1);
    cudaFuncSetAttribute(k2_conv2,      cudaFuncAttributeMaxDynamicSharedMemorySize, SM_K2);
    cudaFuncSetAttribute(k3_involution, cudaFuncAttributeMaxDynamicSharedMemorySize, SM_K3);
    cudaFuncSetAttribute(k4a_ln_pw1,    cudaFuncAttributeMaxDynamicSharedMemorySize, SM_K4A);
    cudaFuncSetAttribute(k4b_pw2,       cudaFuncAttributeMaxDynamicSharedMemorySize, SM_K4B);

    k1_conv1<<<256, 256, SM_K1>>>(x, c1w, c1b, bng, bnb, bnm, bnv);
    k2_conv2<<<dim3(256, 4), 256, SM_K2>>>(c2w, c2b);
    k3_involution<<<dim3(8, 8, 8), 256, SM_K3>>>(x);
    k4a_ln_pw1<<<dim3(256, 2), 256, SM_K4A>>>(lng, lnb, p1w, p1b);
    k4b_pw2<<<256, 256, SM_K4B>>>(p2w, p2b, x, out);
}

// round 3
// speedup vs baseline: 2.3967x; 1.8044x over previous
#include <cuda_runtime.h>
#include <cuda_bf16.h>
#include <math.h>

// Problem constants
#define BB   8
#define DIM  128
#define HH   64
#define WW   64
#define HW   4096
#define KK   7
#define GG   8
#define GC   16
#define C1   32
#define C2   392
#define NPIX 32768

// -------- scratch (device globals) --------
__device__ float    g_t[BB * C1 * HW];        // conv1+bn+relu, NCHW fp32 (4 MB)
__device__ float    g_wgt[BB * C2 * HW];      // involution weights, NCHW fp32 (51 MB)
__device__ float    g_y[NPIX * DIM];          // involution out, NHWC fp32 (17 MB)
__device__ unsigned g_yn[64 * NPIX];          // LN out, bf16 pairs along c: [c/2][px] (8 MB)
__device__ unsigned g_hb[128 * NPIX];         // pw1+gelu out, bf16 [f][px] viewed as u32 pairs along px (16 MB)

// -------- helpers --------
__device__ __forceinline__ unsigned packbf(float lo, float hi) {
    unsigned r; asm("cvt.rn.bf16x2.f32 %0, %1, %2;" : "=r"(r) : "f"(hi), "f"(lo)); return r;
}
__device__ __forceinline__ void mma16(float* c, unsigned a0, unsigned a1,
                                      unsigned a2, unsigned a3,
                                      unsigned b0, unsigned b1) {
    asm volatile(
        "mma.sync.aligned.m16n8k16.row.col.f32.bf16.bf16.f32 "
        "{%0,%1,%2,%3}, {%4,%5,%6,%7}, {%8,%9}, {%0,%1,%2,%3};\n"
        : "+f"(c[0]), "+f"(c[1]), "+f"(c[2]), "+f"(c[3])
        : "r"(a0), "r"(a1), "r"(a2), "r"(a3), "r"(b0), "r"(b1));
}

// =====================================================================
// K1: t = relu(bn(conv1(x)))  — bf16 MMA, M=32, N=128px, K=128
// grid 256, block 256. smem: wAu[32][68] + xsu[64][136] + 64
// =====================================================================
__global__ __launch_bounds__(256) void k1_conv1(
    const float* __restrict__ x,  const float* __restrict__ w1,
    const float* __restrict__ b1, const float* __restrict__ bng,
    const float* __restrict__ bnb, const float* __restrict__ bnm,
    const float* __restrict__ bnv) {
    extern __shared__ unsigned smu[];
    unsigned* wAu = smu;                 // 32*68
    unsigned* xsu = smu + 32 * 68;       // 64*136
    float* bs = (float*)(xsu + 64 * 136);
    float* ss = bs + 32;
    int tid = threadIdx.x;

    if (tid < 32) {
        float sc = bng[tid] * rsqrtf(bnv[tid] + 1e-5f);
        ss[tid] = sc;
        bs[tid] = b1[tid] * sc + bnb[tid] - bnm[tid] * sc;
    }
    __syncthreads();
    for (int i = tid; i < 32 * 64; i += 256) {
        int o = i >> 6, c2 = i & 63;
        float sc = ss[o];
        wAu[o * 68 + c2] = packbf(w1[o * 128 + 2 * c2] * sc, w1[o * 128 + 2 * c2 + 1] * sc);
    }
    int pb = blockIdx.x * 128, b = pb >> 12, pin = pb & 4095;
    const float* xb = x + b * DIM * HW + pin;
    for (int i = tid; i < 64 * 128; i += 256) {
        int c2 = i >> 7, p = i & 127;
        xsu[c2 * 136 + p] = packbf(xb[(2 * c2) * HW + p], xb[(2 * c2 + 1) * HW + p]);
    }
    __syncthreads();

    int wid = tid >> 5, lane = tid & 31, gid = lane >> 2, ctid = lane & 3;
    int m = wid & 1, ng = wid >> 1;
    int px0 = ng * 32;
    float acc[4][4];
#pragma unroll
    for (int a = 0; a < 4; a++)
#pragma unroll
        for (int q = 0; q < 4; q++) acc[a][q] = 0.f;

#pragma unroll
    for (int s = 0; s < 8; s++) {
        const unsigned* ap = wAu + (m * 16 + gid) * 68 + s * 8 + ctid;
        unsigned a0 = ap[0], a1 = ap[8 * 68], a2 = ap[4], a3 = ap[8 * 68 + 4];
#pragma unroll
        for (int nt = 0; nt < 4; nt++) {
            int pxn = px0 + nt * 8 + gid;
            unsigned b0 = xsu[(s * 8 + ctid) * 136 + pxn];
            unsigned b1v = xsu[(s * 8 + ctid + 4) * 136 + pxn];
            mma16(acc[nt], a0, a1, a2, a3, b0, b1v);
        }
    }
    float* tb = g_t + b * C1 * HW + pin;
    int o0 = m * 16 + gid;
#pragma unroll
    for (int nt = 0; nt < 4; nt++) {
        int px = px0 + nt * 8 + 2 * ctid;
        float b0v = bs[o0], b1v = bs[o0 + 8];
        *(float2*)(tb + o0 * HW + px) =
            make_float2(fmaxf(acc[nt][0] + b0v, 0.f), fmaxf(acc[nt][1] + b0v, 0.f));
        *(float2*)(tb + (o0 + 8) * HW + px) =
            make_float2(fmaxf(acc[nt][2] + b1v, 0.f), fmaxf(acc[nt][3] + b1v, 0.f));
    }
}

// =====================================================================
// K2: wgt = conv2(t) — bf16 MMA, M=128/block (392→512), N=128, K=32
// grid (256,4), block 256. smem: wAu[128][20] + tsu[16][136] + 128
// =====================================================================
__global__ __launch_bounds__(256) void k2_conv2(
    const float* __restrict__ w2, const float* __restrict__ b2) {
    extern __shared__ unsigned smu[];
    unsigned* wAu = smu;                 // 128*20
    unsigned* tsu = smu + 128 * 20;      // 16*136
    float* bsm = (float*)(tsu + 16 * 136);
    int tid = threadIdx.x;
    int o0 = blockIdx.y * 128;

    for (int i = tid; i < 128 * 16; i += 256) {
        int o = i >> 4, c2 = i & 15;
        int go = o0 + o;
        float w0v = (go < C2) ? w2[go * C1 + 2 * c2] : 0.f;
        float w1v = (go < C2) ? w2[go * C1 + 2 * c2 + 1] : 0.f;
        wAu[o * 20 + c2] = packbf(w0v, w1v);
    }
    if (tid < 128) bsm[tid] = (o0 + tid < C2) ? b2[o0 + tid] : 0.f;
    int pb = blockIdx.x * 128, b = pb >> 12, pin = pb & 4095;
    const float* tbp = g_t + b * C1 * HW + pin;
    for (int i = tid; i < 16 * 128; i += 256) {
        int c2 = i >> 7, p = i & 127;
        tsu[c2 * 136 + p] = packbf(tbp[(2 * c2) * HW + p], tbp[(2 * c2 + 1) * HW + p]);
    }
    __syncthreads();

    int wid = tid >> 5, lane = tid & 31, gid = lane >> 2, ctid = lane & 3;
    int m = wid & 3, ng = wid >> 2;
    float acc[2][8][4];
#pragma unroll
    for (int mt = 0; mt < 2; mt++)
#pragma unroll
        for (int nt = 0; nt < 8; nt++)
#pragma unroll
            for (int q = 0; q < 4; q++) acc[mt][nt][q] = 0.f;

#pragma unroll
    for (int s = 0; s < 2; s++) {
        unsigned a[2][4];
#pragma unroll
        for (int mt = 0; mt < 2; mt++) {
            const unsigned* ap = wAu + (m * 32 + mt * 16 + gid) * 20 + s * 8 + ctid;
            a[mt][0] = ap[0]; a[mt][1] = ap[8 * 20];
            a[mt][2] = ap[4]; a[mt][3] = ap[8 * 20 + 4];
        }
#pragma unroll
        for (int nt = 0; nt < 8; nt++) {
            int pxn = ng * 64 + nt * 8 + gid;
            unsigned b0 = tsu[(s * 8 + ctid) * 136 + pxn];
            unsigned b1v = tsu[(s * 8 + ctid + 4) * 136 + pxn];
#pragma unroll
            for (int mt = 0; mt < 2; mt++)
                mma16(acc[mt][nt], a[mt][0], a[mt][1], a[mt][2], a[mt][3], b0, b1v);
        }
    }
    float* wout = g_wgt + b * C2 * HW + pin;
#pragma unroll
    for (int mt = 0; mt < 2; mt++) {
        int orow = m * 32 + mt * 16 + gid;
        int go0 = o0 + orow, go1 = go0 + 8;
        float bb0 = bsm[orow], bb1 = bsm[orow + 8];
#pragma unroll
        for (int nt = 0; nt < 8; nt++) {
            int px = ng * 64 + nt * 8 + 2 * ctid;
            if (go0 < C2)
                *(float2*)(wout + go0 * HW + px) =
                    make_float2(acc[mt][nt][0] + bb0, acc[mt][nt][1] + bb0);
            if (go1 < C2)
                *(float2*)(wout + go1 * HW + px) =
                    make_float2(acc[mt][nt][2] + bb1, acc[mt][nt][3] + bb1);
        }
    }
}

// =====================================================================
// K3: involution, 4 px/thread with sliding window.
// grid (8,8,8), block 128.
// =====================================================================
#define XS_ROW 72
#define XS_CH  (14 * 72)
__global__ __launch_bounds__(128) void k3_involution(const float* __restrict__ x) {
    extern __shared__ float xs[];     // 16*14*72
    int tid = threadIdx.x;
    int h0 = blockIdx.x * 8;
    int g  = blockIdx.y;
    int b  = blockIdx.z;

    for (int i = tid; i < GC * XS_CH; i += 128) xs[i] = 0.f;
    __syncthreads();
    const float* xg = x + (b * DIM + g * GC) * HW;
    for (int idx = tid; idx < GC * 14 * 64; idx += 128) {
        int gc = idx / (14 * 64);
        int rem = idx - gc * (14 * 64);
        int rr = rem >> 6, ww = rem & 63;
        int hh = h0 - 3 + rr;
        if (hh >= 0 && hh < HH)
            xs[gc * XS_CH + rr * XS_ROW + ww + 3] = xg[gc * HW + hh * WW + ww];
    }
    __syncthreads();

    int r  = tid >> 4;          // 0..7
    int w0 = (tid & 15) * 4;    // 0..60
    float acc[GC][4];
#pragma unroll
    for (int gc = 0; gc < GC; gc++)
#pragma unroll
        for (int l = 0; l < 4; l++) acc[gc][l] = 0.f;

    const float* wp = g_wgt + (b * C2 + g * 49) * HW + (h0 + r) * WW + w0;
#pragma unroll
    for (int i = 0; i < KK; i++) {
        float4 wv[KK];
#pragma unroll
        for (int j = 0; j < KK; j++)
            wv[j] = *(const float4*)(wp + (i * KK + j) * HW);
#pragma unroll
        for (int gc = 0; gc < GC; gc++) {
            const float* xrow = xs + gc * XS_CH + (r + i) * XS_ROW + w0;
            float4 xa = *(const float4*)(xrow);
            float4 xb4 = *(const float4*)(xrow + 4);
            float4 xc = *(const float4*)(xrow + 8);
            float xw[12] = {xa.x, xa.y, xa.z, xa.w, xb4.x, xb4.y, xb4.z, xb4.w,
                            xc.x, xc.y, xc.z, xc.w};
#pragma unroll
            for (int j = 0; j < KK; j++) {
                acc[gc][0] += wv[j].x * xw[j];
                acc[gc][1] += wv[j].y * xw[j + 1];
                acc[gc][2] += wv[j].z * xw[j + 2];
                acc[gc][3] += wv[j].w * xw[j + 3];
            }
        }
    }
#pragma unroll
    for (int l = 0; l < 4; l++) {
        float* yo = g_y + (b * HW + (h0 + r) * WW + w0 + l) * DIM + g * GC;
#pragma unroll
        for (int q = 0; q < 4; q++)
            *(float4*)(yo + q * 4) = make_float4(acc[q*4][l], acc[q*4+1][l],
                                                 acc[q*4+2][l], acc[q*4+3][l]);
    }
}

// =====================================================================
// K4LN: LayerNorm over g_y, writes bf16 pairs to g_yn [c/2][px]
// grid 256, block 256 (2 threads/px)
// =====================================================================
__global__ __launch_bounds__(256) void k4_ln(
    const float* __restrict__ lng_g, const float* __restrict__ lnb_g) {
    __shared__ float lng[128], lnb[128];
    int tid = threadIdx.x;
    if (tid < 128) { lng[tid] = lng_g[tid]; lnb[tid] = lnb_g[tid]; }
    __syncthreads();

    int p = blockIdx.x * 128 + (tid >> 1);
    int half = tid & 1;
    const float* yp = g_y + p * DIM + half * 64;
    float4 v[16];
    float s = 0.f, q = 0.f;
#pragma unroll
    for (int i = 0; i < 16; i++) {
        v[i] = *(const float4*)(yp + i * 4);
        s += v[i].x + v[i].y + v[i].z + v[i].w;
        q += v[i].x*v[i].x + v[i].y*v[i].y + v[i].z*v[i].z + v[i].w*v[i].w;
    }
    s += __shfl_xor_sync(0xffffffffu, s, 1);
    q += __shfl_xor_sync(0xffffffffu, q, 1);
    float mu = s * (1.f / 128.f);
    float var = q * (1.f / 128.f) - mu * mu;
    float rs = rsqrtf(var + 1e-6f);
#pragma unroll
    for (int i = 0; i < 16; i++) {
        int c = half * 64 + i * 4;
        float n0 = (v[i].x - mu) * rs * lng[c+0] + lnb[c+0];
        float n1 = (v[i].y - mu) * rs * lng[c+1] + lnb[c+1];
        float n2 = (v[i].z - mu) * rs * lng[c+2] + lnb[c+2];
        float n3 = (v[i].w - mu) * rs * lng[c+3] + lnb[c+3];
        g_yn[(c >> 1) * NPIX + p]       = packbf(n0, n1);
        g_yn[((c >> 1) + 1) * NPIX + p] = packbf(n2, n3);
    }
}

// =====================================================================
// K4A: pw1 + exact GELU — bf16 MMA. M=128 f/block (of 256), N=128 px,
// K=128. grid (256,2), block 256. smem: w1u[128][68] + ysu[64][136]
// =====================================================================
__global__ __launch_bounds__(256) void k4a_pw1(
    const float* __restrict__ p1w, const float* __restrict__ p1b) {
    extern __shared__ unsigned smu[];
    unsigned* w1u = smu;                 // 128*68
    unsigned* ysu = smu + 128 * 68;      // 64*136
    float* b1s = (float*)(ysu + 64 * 136);
    int tid = threadIdx.x;
    int f0 = blockIdx.y * 128;
    int pb = blockIdx.x * 128;

    for (int i = tid; i < 128 * 64; i += 256) {
        int f = i >> 6, c2 = i & 63;
        const float2 wv = *(const float2*)(p1w + (f0 + f) * 128 + 2 * c2);
        w1u[f * 68 + c2] = packbf(wv.x, wv.y);
    }
    if (tid < 128) b1s[tid] = p1b[f0 + tid];
    for (int i = tid; i < 64 * 128; i += 256) {
        int c2 = i >> 7, p = i & 127;
        ysu[c2 * 136 + p] = g_yn[c2 * NPIX + pb + p];
    }
    __syncthreads();

    int wid = tid >> 5, lane = tid & 31, gid = lane >> 2, ctid = lane & 3;
    int m = wid & 3, ng = wid >> 2;
    float acc[2][8][4];
#pragma unroll
    for (int mt = 0; mt < 2; mt++)
#pragma unroll
        for (int nt = 0; nt < 8; nt++)
#pragma unroll
            for (int q = 0; q < 4; q++) acc[mt][nt][q] = 0.f;

#pragma unroll
    for (int s = 0; s < 8; s++) {
        unsigned a[2][4];
#pragma unroll
        for (int mt = 0; mt < 2; mt++) {
            const unsigned* ap = w1u + (m * 32 + mt * 16 + gid) * 68 + s * 8 + ctid;
            a[mt][0] = ap[0]; a[mt][1] = ap[8 * 68];
            a[mt][2] = ap[4]; a[mt][3] = ap[8 * 68 + 4];
        }
#pragma unroll
        for (int nt = 0; nt < 8; nt++) {
            int pxn = ng * 64 + nt * 8 + gid;
            unsigned b0 = ysu[(s * 8 + ctid) * 136 + pxn];
            unsigned b1v = ysu[(s * 8 + ctid + 4) * 136 + pxn];
#pragma unroll
            for (int mt = 0; mt < 2; mt++)
                mma16(acc[mt][nt], a[mt][0], a[mt][1], a[mt][2], a[mt][3], b0, b1v);
        }
    }
    const float ISQ2 = 0.70710678118654752f;
#pragma unroll
    for (int mt = 0; mt < 2; mt++) {
        int frow = m * 32 + mt * 16 + gid;
        float bb0 = b1s[frow], bb1 = b1s[frow + 8];
        int fg0 = f0 + frow, fg1 = fg0 + 8;
#pragma unroll
        for (int nt = 0; nt < 8; nt++) {
            int px = pb + ng * 64 + nt * 8 + 2 * ctid;
            float z0 = acc[mt][nt][0] + bb0, z1 = acc[mt][nt][1] + bb0;
            float z2 = acc[mt][nt][2] + bb1, z3 = acc[mt][nt][3] + bb1;
            float g0 = 0.5f * z0 * (1.f + erff(z0 * ISQ2));
            float g1 = 0.5f * z1 * (1.f + erff(z1 * ISQ2));
            float g2 = 0.5f * z2 * (1.f + erff(z2 * ISQ2));
            float g3 = 0.5f * z3 * (1.f + erff(z3 * ISQ2));
            g_hb[(fg0 * NPIX + px) >> 1] = packbf(g0, g1);
            g_hb[(fg1 * NPIX + px) >> 1] = packbf(g2, g3);
        }
    }
}

// =====================================================================
// K4B: pw2 + bias + residual — bf16 MMA. M=128 c, N=128 px, K=256 in 2
// chunks. grid 256, block 256. smem: w2u[128][68] + hsu[64][136]
// =====================================================================
__global__ __launch_bounds__(256) void k4b_pw2(
    const float* __restrict__ p2w, const float* __restrict__ p2b,
    const float* __restrict__ x,   float* __restrict__ out) {
    extern __shared__ unsigned smu[];
    unsigned* w2u = smu;                 // 128*68
    unsigned* hsu = smu + 128 * 68;      // 64*136
    float* b2s = (float*)(hsu + 64 * 136);
    int tid = threadIdx.x;
    int pb = blockIdx.x * 128, b = pb >> 12, pin = pb & 4095;
    if (tid < 128) b2s[tid] = p2b[tid];

    int wid = tid >> 5, lane = tid & 31, gid = lane >> 2, ctid = lane & 3;
    int m = wid & 3, ng = wid >> 2;
    float acc[2][8][4];
#pragma unroll
    for (int mt = 0; mt < 2; mt++)
#pragma unroll
        for (int nt = 0; nt < 8; nt++)
#pragma unroll
            for (int q = 0; q < 4; q++) acc[mt][nt][q] = 0.f;

    const unsigned short* h16 = (const unsigned short*)g_hb;
    for (int kc = 0; kc < 2; kc++) {
        __syncthreads();
        for (int i = tid; i < 128 * 64; i += 256) {
            int c = i >> 6, f2 = i & 63;
            const float2 wv = *(const float2*)(p2w + c * 256 + kc * 128 + 2 * f2);
            w2u[c * 68 + f2] = packbf(wv.x, wv.y);
        }
        for (int i = tid; i < 64 * 128; i += 256) {
            int f2 = i >> 7, p = i & 127;
            int f = kc * 128 + 2 * f2;
            unsigned lo = h16[f * NPIX + pb + p];
            unsigned hi = h16[(f + 1) * NPIX + pb + p];
            hsu[f2 * 136 + p] = lo | (hi << 16);
        }
        __syncthreads();
#pragma unroll
        for (int s = 0; s < 8; s++) {
            unsigned a[2][4];
#pragma unroll
            for (int mt = 0; mt < 2; mt++) {
                const unsigned* ap = w2u + (m * 32 + mt * 16 + gid) * 68 + s * 8 + ctid;
                a[mt][0] = ap[0]; a[mt][1] = ap[8 * 68];
                a[mt][2] = ap[4]; a[mt][3] = ap[8 * 68 + 4];
            }
#pragma unroll
            for (int nt = 0; nt < 8; nt++) {
                int pxn = ng * 64 + nt * 8 + gid;
                unsigned b0 = hsu[(s * 8 + ctid) * 136 + pxn];
                unsigned b1v = hsu[(s * 8 + ctid + 4) * 136 + pxn];
#pragma unroll
                for (int mt = 0; mt < 2; mt++)
                    mma16(acc[mt][nt], a[mt][0], a[mt][1], a[mt][2], a[mt][3], b0, b1v);
            }
        }
    }
#pragma unroll
    for (int mt = 0; mt < 2; mt++) {
        int crow = m * 32 + mt * 16 + gid;
        float bb0 = b2s[crow], bb1 = b2s[crow + 8];
#pragma unroll
        for (int nt = 0; nt < 8; nt++) {
            int px = ng * 64 + nt * 8 + 2 * ctid;
            int base0 = (b * DIM + crow) * HW + pin + px;
            int base1 = base0 + 8 * HW;
            float2 x0 = *(const float2*)(x + base0);
            float2 x1 = *(const float2*)(x + base1);
            *(float2*)(out + base0) =
                make_float2(acc[mt][nt][0] + bb0 + x0.x, acc[mt][nt][1] + bb0 + x0.y);
            *(float2*)(out + base1) =
                make_float2(acc[mt][nt][2] + bb1 + x1.x, acc[mt][nt][3] + bb1 + x1.y);
        }
    }
}

// =====================================================================
extern "C" void kernel_launch(void* const* d_in, const int* in_sizes, int n_in,
                              void* d_out, int out_size) {
    const float* x    = (const float*)d_in[0];
    const float* c1w  = (const float*)d_in[1];
    const float* c1b  = (const float*)d_in[2];
    const float* bng  = (const float*)d_in[3];
    const float* bnb  = (const float*)d_in[4];
    const float* bnm  = (const float*)d_in[5];
    const float* bnv  = (const float*)d_in[6];
    const float* c2w  = (const float*)d_in[7];
    const float* c2b  = (const float*)d_in[8];
    const float* lng  = (const float*)d_in[9];
    const float* lnb  = (const float*)d_in[10];
    const float* p1w  = (const float*)d_in[11];
    const float* p1b  = (const float*)d_in[12];
    const float* p2w  = (const float*)d_in[13];
    const float* p2b  = (const float*)d_in[14];
    float* out = (float*)d_out;

    const int SM_K1  = (32 * 68 + 64 * 136 + 64) * 4;
    const int SM_K2  = (128 * 20 + 16 * 136 + 128) * 4;
    const int SM_K3  = 16 * 14 * 72 * 4;
    const int SM_K4A = (128 * 68 + 64 * 136 + 128) * 4;
    const int SM_K4B = (128 * 68 + 64 * 136 + 128) * 4;

    cudaFuncSetAttribute(k1_conv1,      cudaFuncAttributeMaxDynamicSharedMemorySize, SM_K1);
    cudaFuncSetAttribute(k2_conv2,      cudaFuncAttributeMaxDynamicSharedMemorySize, SM_K2);
    cudaFuncSetAttribute(k3_involution, cudaFuncAttributeMaxDynamicSharedMemorySize, SM_K3);
    cudaFuncSetAttribute(k4a_pw1,       cudaFuncAttributeMaxDynamicSharedMemorySize, SM_K4A);
    cudaFuncSetAttribute(k4b_pw2,       cudaFuncAttributeMaxDynamicSharedMemorySize, SM_K4B);

    k1_conv1<<<256, 256, SM_K1>>>(x, c1w, c1b, bng, bnb, bnm, bnv);
    k2_conv2<<<dim3(256, 4), 256, SM_K2>>>(c2w, c2b);
    k3_involution<<<dim3(8, 8, 8), 128, SM_K3>>>(x);
    k4_ln<<<256, 256>>>(lng, lnb);
    k4a_pw1<<<dim3(256, 2), 256, SM_K4A>>>(p1w, p1b);
    k4b_pw2<<<256, 256, SM_K4B>>>(p2w, p2b, x, out);
}

// round 4
// speedup vs baseline: 2.5002x; 1.0432x over previous
#include <cuda_runtime.h>
#include <cuda_bf16.h>
#include <math.h>

// Problem constants
#define BB   8
#define DIM  128
#define HH   64
#define WW   64
#define HW   4096
#define KK   7
#define GG   8
#define GC   16
#define C1   32
#define C2   392
#define NPIX 32768

// -------- scratch (device globals) --------
__device__ float    g_t[BB * C1 * HW];        // conv1+bn+relu, NCHW fp32 (4 MB)
__device__ float    g_y[NPIX * DIM];          // involution out, NHWC fp32 (17 MB)
__device__ unsigned g_yn[NPIX * 64];          // LN out, bf16 pairs along c, [px][c/2] (8 MB)
__device__ unsigned g_hb[128 * NPIX];         // pw1+gelu out, bf16 [f][px] as u32 px-pairs (16 MB)

// -------- helpers --------
__device__ __forceinline__ unsigned packbf(float lo, float hi) {
    unsigned r; asm("cvt.rn.bf16x2.f32 %0, %1, %2;" : "=r"(r) : "f"(hi), "f"(lo)); return r;
}
__device__ __forceinline__ void mma16(float* c, unsigned a0, unsigned a1,
                                      unsigned a2, unsigned a3,
                                      unsigned b0, unsigned b1) {
    asm volatile(
        "mma.sync.aligned.m16n8k16.row.col.f32.bf16.bf16.f32 "
        "{%0,%1,%2,%3}, {%4,%5,%6,%7}, {%8,%9}, {%0,%1,%2,%3};\n"
        : "+f"(c[0]), "+f"(c[1]), "+f"(c[2]), "+f"(c[3])
        : "r"(a0), "r"(a1), "r"(a2), "r"(a3), "r"(b0), "r"(b1));
}

// =====================================================================
// K1: t = relu(bn(conv1(x)))  — bf16 MMA, M=32, N=128px, K=128
// =====================================================================
__global__ __launch_bounds__(256) void k1_conv1(
    const float* __restrict__ x,  const float* __restrict__ w1,
    const float* __restrict__ b1, const float* __restrict__ bng,
    const float* __restrict__ bnb, const float* __restrict__ bnm,
    const float* __restrict__ bnv) {
    extern __shared__ unsigned smu[];
    unsigned* wAu = smu;                 // 32*68
    unsigned* xsu = smu + 32 * 68;       // 64*136
    float* bs = (float*)(xsu + 64 * 136);
    float* ss = bs + 32;
    int tid = threadIdx.x;

    if (tid < 32) {
        float sc = bng[tid] * rsqrtf(bnv[tid] + 1e-5f);
        ss[tid] = sc;
        bs[tid] = b1[tid] * sc + bnb[tid] - bnm[tid] * sc;
    }
    __syncthreads();
    for (int i = tid; i < 32 * 64; i += 256) {
        int o = i >> 6, c2 = i & 63;
        float sc = ss[o];
        wAu[o * 68 + c2] = packbf(w1[o * 128 + 2 * c2] * sc, w1[o * 128 + 2 * c2 + 1] * sc);
    }
    int pb = blockIdx.x * 128, b = pb >> 12, pin = pb & 4095;
    const float* xb = x + b * DIM * HW + pin;
    for (int i = tid; i < 64 * 128; i += 256) {
        int c2 = i >> 7, p = i & 127;
        xsu[c2 * 136 + p] = packbf(xb[(2 * c2) * HW + p], xb[(2 * c2 + 1) * HW + p]);
    }
    __syncthreads();

    int wid = tid >> 5, lane = tid & 31, gid = lane >> 2, ctid = lane & 3;
    int m = wid & 1, ng = wid >> 1;
    int px0 = ng * 32;
    float acc[4][4];
#pragma unroll
    for (int a = 0; a < 4; a++)
#pragma unroll
        for (int q = 0; q < 4; q++) acc[a][q] = 0.f;

#pragma unroll
    for (int s = 0; s < 8; s++) {
        const unsigned* ap = wAu + (m * 16 + gid) * 68 + s * 8 + ctid;
        unsigned a0 = ap[0], a1 = ap[8 * 68], a2 = ap[4], a3 = ap[8 * 68 + 4];
#pragma unroll
        for (int nt = 0; nt < 4; nt++) {
            int pxn = px0 + nt * 8 + gid;
            unsigned b0 = xsu[(s * 8 + ctid) * 136 + pxn];
            unsigned b1v = xsu[(s * 8 + ctid + 4) * 136 + pxn];
            mma16(acc[nt], a0, a1, a2, a3, b0, b1v);
        }
    }
    float* tb = g_t + b * C1 * HW + pin;
    int o0 = m * 16 + gid;
#pragma unroll
    for (int nt = 0; nt < 4; nt++) {
        int px = px0 + nt * 8 + 2 * ctid;
        float b0v = bs[o0], b1v = bs[o0 + 8];
        *(float2*)(tb + o0 * HW + px) =
            make_float2(fmaxf(acc[nt][0] + b0v, 0.f), fmaxf(acc[nt][1] + b0v, 0.f));
        *(float2*)(tb + (o0 + 8) * HW + px) =
            make_float2(fmaxf(acc[nt][2] + b1v, 0.f), fmaxf(acc[nt][3] + b1v, 0.f));
    }
}

// =====================================================================
// K23: fused conv2 + involution.  grid (8 strips, 8 groups, 8 b), 256 thr.
// Phase A: wgt[49][512] = w2_g @ t  (bf16 MMA, smem-resident result)
// Phase B: 7x7 stencil from smem wgt + smem x halo tile → g_y NHWC
// smem: wgt 49*520 f32 | region shared by (tsu 16*520 u32 + wAu 64*20 + bsm)
//       then (xs 16*14*72 f32)
// =====================================================================
#define XS_ROW 72
#define XS_CH  (14 * 72)
#define WGT_S  520
__global__ __launch_bounds__(256) void k23_conv2_inv(
    const float* __restrict__ x, const float* __restrict__ w2,
    const float* __restrict__ b2) {
    extern __shared__ float smf[];
    float* wgt = smf;                          // 49*520 = 25480 f
    float* xs  = smf + 49 * WGT_S;             // 16128 f
    unsigned* tsu = (unsigned*)xs;             // 16*520 u32 (overlaps xs)
    unsigned* wAu = tsu + 16 * WGT_S;          // 64*20
    float* bsm = (float*)(wAu + 64 * 20);      // 64
    int tid = threadIdx.x;
    int h0 = blockIdx.x * 8;
    int g  = blockIdx.y;
    int b  = blockIdx.z;

    // ---- Phase A loads ----
    const float* tb = g_t + b * C1 * HW + h0 * 64;
    for (int i = tid; i < 16 * 512; i += 256) {
        int c2 = i >> 9, px = i & 511;
        tsu[c2 * WGT_S + px] = packbf(tb[(2 * c2) * HW + px], tb[(2 * c2 + 1) * HW + px]);
    }
    for (int i = tid; i < 64 * 16; i += 256) {
        int o = i >> 4, c2 = i & 15;
        float a0 = 0.f, a1 = 0.f;
        if (o < 49) {
            int go = g * 49 + o;
            a0 = w2[go * C1 + 2 * c2];
            a1 = w2[go * C1 + 2 * c2 + 1];
        }
        wAu[o * 20 + c2] = packbf(a0, a1);
    }
    if (tid < 64) bsm[tid] = (tid < 49) ? b2[g * 49 + tid] : 0.f;
    __syncthreads();

    // ---- Phase A MMA: M=64(49), N=512, K=32 in two n-halves ----
    int wid = tid >> 5, lane = tid & 31, gid = lane >> 2, ctid = lane & 3;
    int m = wid & 3, ng = wid >> 2;
    int orow = m * 16 + gid;
    float bb0 = bsm[orow], bb1 = bsm[orow + 8];
#pragma unroll
    for (int nh = 0; nh < 2; nh++) {
        float acc[16][4];
#pragma unroll
        for (int nt = 0; nt < 16; nt++)
#pragma unroll
            for (int q = 0; q < 4; q++) acc[nt][q] = 0.f;
#pragma unroll
        for (int s = 0; s < 2; s++) {
            const unsigned* ap = wAu + orow * 20 + s * 8 + ctid;
            unsigned a0 = ap[0], a1 = ap[8 * 20], a2 = ap[4], a3 = ap[8 * 20 + 4];
#pragma unroll
            for (int nt = 0; nt < 16; nt++) {
                int pxn = nh * 256 + ng * 128 + nt * 8 + gid;
                unsigned b0 = tsu[(s * 8 + ctid) * WGT_S + pxn];
                unsigned b1v = tsu[(s * 8 + ctid + 4) * WGT_S + pxn];
                mma16(acc[nt], a0, a1, a2, a3, b0, b1v);
            }
        }
#pragma unroll
        for (int nt = 0; nt < 16; nt++) {
            int px = nh * 256 + ng * 128 + nt * 8 + 2 * ctid;
            if (orow < 49)
                *(float2*)(wgt + orow * WGT_S + px) =
                    make_float2(acc[nt][0] + bb0, acc[nt][1] + bb0);
            if (orow + 8 < 49)
                *(float2*)(wgt + (orow + 8) * WGT_S + px) =
                    make_float2(acc[nt][2] + bb1, acc[nt][3] + bb1);
        }
    }
    __syncthreads();   // wgt complete; tsu/wAu dead

    // ---- Phase B: x halo tile (overwrites tsu region) ----
    for (int i = tid; i < GC * XS_CH; i += 256) xs[i] = 0.f;
    __syncthreads();
    const float* xg = x + (b * DIM + g * GC) * HW;
    for (int idx = tid; idx < GC * 14 * 64; idx += 256) {
        int gc = idx / (14 * 64);
        int rem = idx - gc * (14 * 64);
        int rr = rem >> 6, ww = rem & 63;
        int hh = h0 - 3 + rr;
        if (hh >= 0 && hh < HH)
            xs[gc * XS_CH + rr * XS_ROW + ww + 3] = xg[gc * HW + hh * WW + ww];
    }
    __syncthreads();

    // ---- stencil: thread = (gc-half, 4 px) ----
    int gcH = tid & 1;
    int pxq = tid >> 1;                  // 0..127
    int r = pxq >> 4, w0 = (pxq & 15) * 4;
    float acc[8][4];
#pragma unroll
    for (int gc8 = 0; gc8 < 8; gc8++)
#pragma unroll
        for (int l = 0; l < 4; l++) acc[gc8][l] = 0.f;

    const float* wp = wgt + r * 64 + w0;
#pragma unroll
    for (int i = 0; i < KK; i++) {
        float4 wv[KK];
#pragma unroll
        for (int j = 0; j < KK; j++)
            wv[j] = *(const float4*)(wp + (i * KK + j) * WGT_S);
#pragma unroll
        for (int gc8 = 0; gc8 < 8; gc8++) {
            int gc = gcH * 8 + gc8;
            const float* xrow = xs + gc * XS_CH + (r + i) * XS_ROW + w0;
            float4 xa = *(const float4*)(xrow);
            float4 xb4 = *(const float4*)(xrow + 4);
            float4 xc = *(const float4*)(xrow + 8);
            float xw[12] = {xa.x, xa.y, xa.z, xa.w, xb4.x, xb4.y, xb4.z, xb4.w,
                            xc.x, xc.y, xc.z, xc.w};
#pragma unroll
            for (int j = 0; j < KK; j++) {
                acc[gc8][0] += wv[j].x * xw[j];
                acc[gc8][1] += wv[j].y * xw[j + 1];
                acc[gc8][2] += wv[j].z * xw[j + 2];
                acc[gc8][3] += wv[j].w * xw[j + 3];
            }
        }
    }
#pragma unroll
    for (int l = 0; l < 4; l++) {
        float* yo = g_y + (b * HW + (h0 + r) * WW + w0 + l) * DIM + g * GC + gcH * 8;
        *(float4*)(yo)     = make_float4(acc[0][l], acc[1][l], acc[2][l], acc[3][l]);
        *(float4*)(yo + 4) = make_float4(acc[4][l], acc[5][l], acc[6][l], acc[7][l]);
    }
}

// =====================================================================
// K4LN: LayerNorm, warp per pixel. g_yn layout [px][c/2] bf16-pairs.
// grid 4096, block 256 (8 px/block)
// =====================================================================
__global__ __launch_bounds__(256) void k4_ln(
    const float* __restrict__ lng_g, const float* __restrict__ lnb_g) {
    __shared__ float lng[128], lnb[128];
    int tid = threadIdx.x;
    if (tid < 128) { lng[tid] = lng_g[tid]; lnb[tid] = lnb_g[tid]; }
    __syncthreads();

    int warp = tid >> 5, lane = tid & 31;
    int p = blockIdx.x * 8 + warp;
    float4 v = *(const float4*)(g_y + p * DIM + lane * 4);
    float s = v.x + v.y + v.z + v.w;
    float q = v.x*v.x + v.y*v.y + v.z*v.z + v.w*v.w;
#pragma unroll
    for (int off = 16; off; off >>= 1) {
        s += __shfl_xor_sync(0xffffffffu, s, off);
        q += __shfl_xor_sync(0xffffffffu, q, off);
    }
    float mu = s * (1.f / 128.f);
    float var = q * (1.f / 128.f) - mu * mu;
    float rs = rsqrtf(var + 1e-6f);
    int c = lane * 4;
    float n0 = (v.x - mu) * rs * lng[c+0] + lnb[c+0];
    float n1 = (v.y - mu) * rs * lng[c+1] + lnb[c+1];
    float n2 = (v.z - mu) * rs * lng[c+2] + lnb[c+2];
    float n3 = (v.w - mu) * rs * lng[c+3] + lnb[c+3];
    g_yn[p * 64 + lane * 2]     = packbf(n0, n1);
    g_yn[p * 64 + lane * 2 + 1] = packbf(n2, n3);
}

// =====================================================================
// K4A: pw1 + exact GELU — bf16 MMA. M=128 f/block (of 256), N=128 px,
// K=128. grid (256,2), block 256. smem: w1u[128][68] + ysu[64][137]
// =====================================================================
__global__ __launch_bounds__(256) void k4a_pw1(
    const float* __restrict__ p1w, const float* __restrict__ p1b) {
    extern __shared__ unsigned smu[];
    unsigned* w1u = smu;                 // 128*68
    unsigned* ysu = smu + 128 * 68;      // 64*137
    float* b1s = (float*)(ysu + 64 * 137);
    int tid = threadIdx.x;
    int f0 = blockIdx.y * 128;
    int pb = blockIdx.x * 128;

    for (int i = tid; i < 128 * 64; i += 256) {
        int f = i >> 6, c2 = i & 63;
        const float2 wv = *(const float2*)(p1w + (f0 + f) * 128 + 2 * c2);
        w1u[f * 68 + c2] = packbf(wv.x, wv.y);
    }
    if (tid < 128) b1s[tid] = p1b[f0 + tid];
    for (int i = tid; i < 128 * 64; i += 256) {
        int p = i >> 6, c2 = i & 63;
        ysu[c2 * 137 + p] = g_yn[(pb + p) * 64 + c2];
    }
    __syncthreads();

    int wid = tid >> 5, lane = tid & 31, gid = lane >> 2, ctid = lane & 3;
    int m = wid & 3, ng = wid >> 2;
    float acc[2][8][4];
#pragma unroll
    for (int mt = 0; mt < 2; mt++)
#pragma unroll
        for (int nt = 0; nt < 8; nt++)
#pragma unroll
            for (int q = 0; q < 4; q++) acc[mt][nt][q] = 0.f;

#pragma unroll
    for (int s = 0; s < 8; s++) {
        unsigned a[2][4];
#pragma unroll
        for (int mt = 0; mt < 2; mt++) {
            const unsigned* ap = w1u + (m * 32 + mt * 16 + gid) * 68 + s * 8 + ctid;
            a[mt][0] = ap[0]; a[mt][1] = ap[8 * 68];
            a[mt][2] = ap[4]; a[mt][3] = ap[8 * 68 + 4];
        }
#pragma unroll
        for (int nt = 0; nt < 8; nt++) {
            int pxn = ng * 64 + nt * 8 + gid;
            unsigned b0 = ysu[(s * 8 + ctid) * 137 + pxn];
            unsigned b1v = ysu[(s * 8 + ctid + 4) * 137 + pxn];
#pragma unroll
            for (int mt = 0; mt < 2; mt++)
                mma16(acc[mt][nt], a[mt][0], a[mt][1], a[mt][2], a[mt][3], b0, b1v);
        }
    }
    const float ISQ2 = 0.70710678118654752f;
#pragma unroll
    for (int mt = 0; mt < 2; mt++) {
        int frow = m * 32 + mt * 16 + gid;
        float bb0 = b1s[frow], bb1 = b1s[frow + 8];
        int fg0 = f0 + frow, fg1 = fg0 + 8;
#pragma unroll
        for (int nt = 0; nt < 8; nt++) {
            int px = pb + ng * 64 + nt * 8 + 2 * ctid;
            float z0 = acc[mt][nt][0] + bb0, z1 = acc[mt][nt][1] + bb0;
            float z2 = acc[mt][nt][2] + bb1, z3 = acc[mt][nt][3] + bb1;
            float g0 = 0.5f * z0 * (1.f + erff(z0 * ISQ2));
            float g1 = 0.5f * z1 * (1.f + erff(z1 * ISQ2));
            float g2 = 0.5f * z2 * (1.f + erff(z2 * ISQ2));
            float g3 = 0.5f * z3 * (1.f + erff(z3 * ISQ2));
            g_hb[(fg0 * NPIX + px) >> 1] = packbf(g0, g1);
            g_hb[(fg1 * NPIX + px) >> 1] = packbf(g2, g3);
        }
    }
}

// =====================================================================
// K4B: pw2 + bias + residual — bf16 MMA. M=128 c, N=128 px, K=256 in 2
// chunks. grid 256, block 256. smem: w2u[128][68] + hsu[64][137]
// =====================================================================
__global__ __launch_bounds__(256) void k4b_pw2(
    const float* __restrict__ p2w, const float* __restrict__ p2b,
    const float* __restrict__ x,   float* __restrict__ out) {
    extern __shared__ unsigned smu[];
    unsigned* w2u = smu;                 // 128*68
    unsigned* hsu = smu + 128 * 68;      // 64*137
    float* b2s = (float*)(hsu + 64 * 137);
    int tid = threadIdx.x;
    int pb = blockIdx.x * 128, b = pb >> 12, pin = pb & 4095;
    if (tid < 128) b2s[tid] = p2b[tid];

    int wid = tid >> 5, lane = tid & 31, gid = lane >> 2, ctid = lane & 3;
    int m = wid & 3, ng = wid >> 2;
    float acc[2][8][4];
#pragma unroll
    for (int mt = 0; mt < 2; mt++)
#pragma unroll
        for (int nt = 0; nt < 8; nt++)
#pragma unroll
            for (int q = 0; q < 4; q++) acc[mt][nt][q] = 0.f;

    for (int kc = 0; kc < 2; kc++) {
        __syncthreads();
        for (int i = tid; i < 128 * 64; i += 256) {
            int c = i >> 6, f2 = i & 63;
            const float2 wv = *(const float2*)(p2w + c * 256 + kc * 128 + 2 * f2);
            w2u[c * 68 + f2] = packbf(wv.x, wv.y);
        }
        // h tile: two coalesced u32 loads (px-pairs) + PRMT repack to f-pairs
        for (int i = tid; i < 64 * 64; i += 256) {
            int f2 = i >> 6, p2 = i & 63;
            int f = kc * 128 + 2 * f2;
            unsigned lo = g_hb[((f * NPIX + pb) >> 1) + p2];
            unsigned hi = g_hb[(((f + 1) * NPIX + pb) >> 1) + p2];
            unsigned r0, r1;
            asm("prmt.b32 %0, %1, %2, 0x5410;" : "=r"(r0) : "r"(lo), "r"(hi));
            asm("prmt.b32 %0, %1, %2, 0x7632;" : "=r"(r1) : "r"(lo), "r"(hi));
            hsu[f2 * 137 + 2 * p2]     = r0;
            hsu[f2 * 137 + 2 * p2 + 1] = r1;
        }
        __syncthreads();
#pragma unroll
        for (int s = 0; s < 8; s++) {
            unsigned a[2][4];
#pragma unroll
            for (int mt = 0; mt < 2; mt++) {
                const unsigned* ap = w2u + (m * 32 + mt * 16 + gid) * 68 + s * 8 + ctid;
                a[mt][0] = ap[0]; a[mt][1] = ap[8 * 68];
                a[mt][2] = ap[4]; a[mt][3] = ap[8 * 68 + 4];
            }
#pragma unroll
            for (int nt = 0; nt < 8; nt++) {
                int pxn = ng * 64 + nt * 8 + gid;
                unsigned b0 = hsu[(s * 8 + ctid) * 137 + pxn];
                unsigned b1v = hsu[(s * 8 + ctid + 4) * 137 + pxn];
#pragma unroll
                for (int mt = 0; mt < 2; mt++)
                    mma16(acc[mt][nt], a[mt][0], a[mt][1], a[mt][2], a[mt][3], b0, b1v);
            }
        }
    }
#pragma unroll
    for (int mt = 0; mt < 2; mt++) {
        int crow = m * 32 + mt * 16 + gid;
        float bb0 = b2s[crow], bb1 = b2s[crow + 8];
#pragma unroll
        for (int nt = 0; nt < 8; nt++) {
            int px = ng * 64 + nt * 8 + 2 * ctid;
            int base0 = (b * DIM + crow) * HW + pin + px;
            int base1 = base0 + 8 * HW;
            float2 x0 = *(const float2*)(x + base0);
            float2 x1 = *(const float2*)(x + base1);
            *(float2*)(out + base0) =
                make_float2(acc[mt][nt][0] + bb0 + x0.x, acc[mt][nt][1] + bb0 + x0.y);
            *(float2*)(out + base1) =
                make_float2(acc[mt][nt][2] + bb1 + x1.x, acc[mt][nt][3] + bb1 + x1.y);
        }
    }
}

// =====================================================================
extern "C" void kernel_launch(void* const* d_in, const int* in_sizes, int n_in,
                              void* d_out, int out_size) {
    const float* x    = (const float*)d_in[0];
    const float* c1w  = (const float*)d_in[1];
    const float* c1b  = (const float*)d_in[2];
    const float* bng  = (const float*)d_in[3];
    const float* bnb  = (const float*)d_in[4];
    const float* bnm  = (const float*)d_in[5];
    const float* bnv  = (const float*)d_in[6];
    const float* c2w  = (const float*)d_in[7];
    const float* c2b  = (const float*)d_in[8];
    const float* lng  = (const float*)d_in[9];
    const float* lnb  = (const float*)d_in[10];
    const float* p1w  = (const float*)d_in[11];
    const float* p1b  = (const float*)d_in[12];
    const float* p2w  = (const float*)d_in[13];
    const float* p2b  = (const float*)d_in[14];
    float* out = (float*)d_out;

    const int SM_K1  = (32 * 68 + 64 * 136 + 64) * 4;
    const int SM_K23 = (49 * WGT_S + GC * XS_CH) * 4;           // 166432
    const int SM_K4A = (128 * 68 + 64 * 137 + 128) * 4;
    const int SM_K4B = (128 * 68 + 64 * 137 + 128) * 4;

    cudaFuncSetAttribute(k1_conv1,      cudaFuncAttributeMaxDynamicSharedMemorySize, SM_K1);
    cudaFuncSetAttribute(k23_conv2_inv, cudaFuncAttributeMaxDynamicSharedMemorySize, SM_K23);
    cudaFuncSetAttribute(k4a_pw1,       cudaFuncAttributeMaxDynamicSharedMemorySize, SM_K4A);
    cudaFuncSetAttribute(k4b_pw2,       cudaFuncAttributeMaxDynamicSharedMemorySize, SM_K4B);

    k1_conv1<<<256, 256, SM_K1>>>(x, c1w, c1b, bng, bnb, bnm, bnv);
    k23_conv2_inv<<<dim3(8, 8, 8), 256, SM_K23>>>(x, c2w, c2b);
    k4_ln<<<4096, 256>>>(lng, lnb);
    k4a_pw1<<<dim3(256, 2), 256, SM_K4A>>>(p1w, p1b);
    k4b_pw2<<<256, 256, SM_K4B>>>(p2w, p2b, x, out);
}